// round 11
// baseline (speedup 1.0000x reference)
#include <cuda_runtime.h>
#include <math.h>

#define NT     2048
#define NB     32
#define ND     64
#define OUT_T  2144
#define KTOP   8

// Padding: +1 per 8. <=2-way for all patterns; XP(8t+q) = 9t+q (contiguous).
#define XP(i) ((i) + ((i) >> 3))
// Mag-plane padding: +1 per 32
#define MP(i) ((i) + ((i) >> 5))

// Scratch (allocation-free): component-major layout [b][j][d] -> warp-coalesced
__device__ float4 g_comps[NB * KTOP * ND];     // {k, A, B, 2cos(w)}

__device__ __forceinline__ float2 cadd(float2 a, float2 b) { return make_float2(a.x + b.x, a.y + b.y); }
__device__ __forceinline__ float2 csub(float2 a, float2 b) { return make_float2(a.x - b.x, a.y - b.y); }
__device__ __forceinline__ float2 cmul(float2 a, float2 b) {
    return make_float2(a.x * b.x - a.y * b.y, a.x * b.y + a.y * b.x);
}
__device__ __forceinline__ float4 f4add(float4 a, float4 b) {
    return make_float4(a.x + b.x, a.y + b.y, a.z + b.z, a.w + b.w);
}
__device__ __forceinline__ float4 f4sub(float4 a, float4 b) {
    return make_float4(a.x - b.x, a.y - b.y, a.z - b.z, a.w - b.w);
}
__device__ __forceinline__ float4 cmul4(float4 a, float2 w) {
    return make_float4(a.x * w.x - a.y * w.y, a.x * w.y + a.y * w.x,
                       a.z * w.x - a.w * w.y, a.z * w.y + a.w * w.x);
}
__device__ __forceinline__ float4 pk(float2 lo, float2 hi, float2 w) {
    float2 a = cmul(lo, w), b = cmul(hi, w);
    return make_float4(a.x, a.y, b.x, b.y);
}

// scalar dft8
__device__ __forceinline__ void dft8(const float2* a, float2* y) {
    float2 z0 = cadd(a[0], a[4]), z1 = csub(a[0], a[4]);
    float2 z2 = cadd(a[2], a[6]), z3 = csub(a[2], a[6]);
    float2 E0 = cadd(z0, z2), E2 = csub(z0, z2);
    float2 E1 = make_float2(z1.x + z3.y, z1.y - z3.x);
    float2 E3 = make_float2(z1.x - z3.y, z1.y + z3.x);
    float2 u0 = cadd(a[1], a[5]), u1 = csub(a[1], a[5]);
    float2 u2 = cadd(a[3], a[7]), u3 = csub(a[3], a[7]);
    float2 O0 = cadd(u0, u2), O2 = csub(u0, u2);
    float2 O1 = make_float2(u1.x + u3.y, u1.y - u3.x);
    float2 O3 = make_float2(u1.x - u3.y, u1.y + u3.x);
    const float s = 0.70710678118654752f;
    float2 T1 = make_float2(s * (O1.x + O1.y), s * (O1.y - O1.x));
    float2 T2 = make_float2(O2.y, -O2.x);
    float2 T3 = make_float2(s * (O3.y - O3.x), -s * (O3.x + O3.y));
    y[0] = cadd(E0, O0); y[4] = csub(E0, O0);
    y[1] = cadd(E1, T1); y[5] = csub(E1, T1);
    y[2] = cadd(E2, T2); y[6] = csub(E2, T2);
    y[3] = cadd(E3, T3); y[7] = csub(E3, T3);
}

// dual (float4) dft8
__device__ __forceinline__ void dft8_4(const float4* a, float4* y) {
    float4 z0 = f4add(a[0], a[4]), z1 = f4sub(a[0], a[4]);
    float4 z2 = f4add(a[2], a[6]), z3 = f4sub(a[2], a[6]);
    float4 E0 = f4add(z0, z2), E2 = f4sub(z0, z2);
    float4 E1 = make_float4(z1.x + z3.y, z1.y - z3.x, z1.z + z3.w, z1.w - z3.z);
    float4 E3 = make_float4(z1.x - z3.y, z1.y + z3.x, z1.z - z3.w, z1.w + z3.z);
    float4 u0 = f4add(a[1], a[5]), u1 = f4sub(a[1], a[5]);
    float4 u2 = f4add(a[3], a[7]), u3 = f4sub(a[3], a[7]);
    float4 O0 = f4add(u0, u2), O2 = f4sub(u0, u2);
    float4 O1 = make_float4(u1.x + u3.y, u1.y - u3.x, u1.z + u3.w, u1.w - u3.z);
    float4 O3 = make_float4(u1.x - u3.y, u1.y + u3.x, u1.z - u3.w, u1.w + u3.z);
    const float s = 0.70710678118654752f;
    float4 T1 = make_float4(s * (O1.x + O1.y), s * (O1.y - O1.x),
                            s * (O1.z + O1.w), s * (O1.w - O1.z));
    float4 T2 = make_float4(O2.y, -O2.x, O2.w, -O2.z);
    float4 T3 = make_float4(s * (O3.y - O3.x), -s * (O3.x + O3.y),
                            s * (O3.w - O3.z), -s * (O3.z + O3.w));
    y[0] = f4add(E0, O0); y[4] = f4sub(E0, O0);
    y[1] = f4add(E1, T1); y[5] = f4sub(E1, T1);
    y[2] = f4add(E2, T2); y[6] = f4sub(E2, T2);
    y[3] = f4add(E3, T3); y[7] = f4sub(E3, T3);
}

// Output position of frequency k (mixed-radix 8,8,4,8 DIF digit reversal)
__device__ __forceinline__ int posk(int k) {
    return ((k >> 8) & 7) | (((k >> 6) & 3) << 3) | (((k >> 3) & 7) << 5) | ((k & 7) << 8);
}

// ---------------------------------------------------------------------------
// Kernel B: TWO packed-real-pair 2048-pt FFTs per block (4 series = one
// float4 column of (b,t,d)); single-pass magnitudes into 4 scalar planes.
// Dynamic smem: X(36864) + M(4x1056x4=16896) + cand(512) = 54272 B.
// ---------------------------------------------------------------------------
__global__ void __launch_bounds__(256) k_fft_topk(const float* __restrict__ x) {
    extern __shared__ char smem[];
    float4* X    = (float4*)smem;                       // XP-padded 2048
    float*  M    = (float*)(smem + 36864);              // 4 planes of MP-padded 1024
    float2* cand = (float2*)(smem + 36864 + 16896);     // 4 series x 16
    int tid  = threadIdx.x;
    int lane = tid & 31;
    int wid  = tid >> 5;
    int b    = blockIdx.x >> 4;
    int dq   = blockIdx.x & 15;         // float4 column: d = 4dq..4dq+3

    // ---- Stage 1: radix-8, stride 256, float4 from gmem; packed stores ----
    {
        float4 v[8];
        const float4* src4 = (const float4*)x + ((size_t)b * NT) * 16 + dq;
#pragma unroll
        for (int m = 0; m < 8; m++) v[m] = src4[(size_t)(tid + (m << 8)) * 16];
        float sw, cw;
        sincospif((float)tid * (1.0f / 1024.0f), &sw, &cw);
        float2 w1 = make_float2(cw, -sw);
        float2 w2 = cmul(w1, w1), w3 = cmul(w2, w1), w4 = cmul(w2, w2);
        float2 w5 = cmul(w3, w2), w6 = cmul(w3, w3), w7 = cmul(w4, w3);
        float2 a[8], lo[8], hi[8];
#pragma unroll
        for (int m = 0; m < 8; m++) a[m] = make_float2(v[m].x, v[m].y);
        dft8(a, lo);
#pragma unroll
        for (int m = 0; m < 8; m++) a[m] = make_float2(v[m].z, v[m].w);
        dft8(a, hi);
        X[XP(tid)]        = make_float4(lo[0].x, lo[0].y, hi[0].x, hi[0].y);
        X[XP(tid + 256)]  = pk(lo[1], hi[1], w1);
        X[XP(tid + 512)]  = pk(lo[2], hi[2], w2);
        X[XP(tid + 768)]  = pk(lo[3], hi[3], w3);
        X[XP(tid + 1024)] = pk(lo[4], hi[4], w4);
        X[XP(tid + 1280)] = pk(lo[5], hi[5], w5);
        X[XP(tid + 1536)] = pk(lo[6], hi[6], w6);
        X[XP(tid + 1792)] = pk(lo[7], hi[7], w7);
    }
    __syncthreads();

    // ---- Stage 2: radix-8, stride 32, within 256-blocks (float4) ----
    {
        int base = (wid << 8) + lane;
        float sw, cw;
        sincospif((float)lane * (1.0f / 128.0f), &sw, &cw);
        float2 w1 = make_float2(cw, -sw);
        float2 w2 = cmul(w1, w1), w3 = cmul(w2, w1), w4 = cmul(w2, w2);
        float2 w5 = cmul(w3, w2), w6 = cmul(w3, w3), w7 = cmul(w4, w3);
        float4 v[8], y[8];
#pragma unroll
        for (int m = 0; m < 8; m++) v[m] = X[XP(base + (m << 5))];
        dft8_4(v, y);
        X[XP(base)]       = y[0];
        X[XP(base + 32)]  = cmul4(y[1], w1);
        X[XP(base + 64)]  = cmul4(y[2], w2);
        X[XP(base + 96)]  = cmul4(y[3], w3);
        X[XP(base + 128)] = cmul4(y[4], w4);
        X[XP(base + 160)] = cmul4(y[5], w5);
        X[XP(base + 192)] = cmul4(y[6], w6);
        X[XP(base + 224)] = cmul4(y[7], w7);
    }
    __syncthreads();

    // ---- Stage 3: radix-4, stride 8 (twiddle depends on tid&7 only) ----
    {
        float sw, cw;
        sincospif((float)(tid & 7) * (1.0f / 16.0f), &sw, &cw);
        float2 w1 = make_float2(cw, -sw);
        float2 w2 = cmul(w1, w1), w3 = cmul(w2, w1);
#pragma unroll
        for (int n = 0; n < 2; n++) {
            int e = tid + (n << 8);
            int base = ((e >> 3) << 5) + (e & 7);
            float4 a = X[XP(base)],      bb = X[XP(base + 8)];
            float4 c = X[XP(base + 16)], d  = X[XP(base + 24)];
            float4 z0 = f4add(a, c), z1 = f4sub(a, c);
            float4 z2 = f4add(bb, d), z3 = f4sub(bb, d);
            float4 y0 = f4add(z0, z2), y2 = f4sub(z0, z2);
            float4 y1 = make_float4(z1.x + z3.y, z1.y - z3.x, z1.z + z3.w, z1.w - z3.z);
            float4 y3 = make_float4(z1.x - z3.y, z1.y + z3.x, z1.z - z3.w, z1.w + z3.z);
            X[XP(base)]      = y0;
            X[XP(base + 8)]  = cmul4(y1, w1);
            X[XP(base + 16)] = cmul4(y2, w2);
            X[XP(base + 24)] = cmul4(y3, w3);
        }
    }
    __syncthreads();

    // ---- Stage 4: radix-8 on 8 consecutive (XP(8t+q) = 9t+q) ----
    {
        int ph = 9 * tid;
        float4 v[8], y[8];
#pragma unroll
        for (int q = 0; q < 8; q++) v[q] = X[ph + q];
        dft8_4(v, y);
#pragma unroll
        for (int q = 0; q < 8; q++) X[ph + q] = y[q];
    }
    __syncthreads();

    // ---- Magnitudes, single pass: all 4 series from one X-pair load ----
    {
        int basek = (lane << 5) | (wid << 2);
        int pb = XP(posk(basek));                    // k-side: +288 per q (exact)
        int mb = MP(basek);                          // +1 per q (k>>5 fixed)
#pragma unroll
        for (int q = 0; q < 4; q++) {
            int k = basek + q;
            float m0, m1, m2, m3;
            if (k == 0) {
                m0 = m1 = m2 = m3 = -1.0f;
            } else {
                float4 t1 = X[pb + 288 * q];
                float4 t2 = X[XP(posk(2048 - k))];
                float e0r = t1.x + t2.x, e0i = t1.y - t2.y;
                float o0r = t1.y + t2.y, o0i = t2.x - t1.x;
                float e1r = t1.z + t2.z, e1i = t1.w - t2.w;
                float o1r = t1.w + t2.w, o1i = t2.z - t1.z;
                m0 = fmaf(e0r, e0r, e0i * e0i);
                m1 = fmaf(o0r, o0r, o0i * o0i);
                m2 = fmaf(e1r, e1r, e1i * e1i);
                m3 = fmaf(o1r, o1r, o1i * o1i);
            }
            int mi = mb + q;
            M[mi]        = m0;
            M[1056 + mi] = m1;
            M[2112 + mi] = m2;
            M[3168 + mi] = m3;
        }
    }
    __syncthreads();

    // ---- Scan: warp w -> series w>>1, half w&1; consecutive k, scalar LDS ----
    {
        int series = wid >> 1;
        int half   = wid & 1;
        const float* Mp = M + series * 1056;
        float bv[KTOP];
        int   bk[KTOP];
#pragma unroll
        for (int q = 0; q < KTOP; q++) { bv[q] = -1.0f; bk[q] = 1; }
#pragma unroll
        for (int it = 0; it < 16; it++) {
            int k = (half << 9) | (it << 5) | lane;
            float mg = Mp[MP(k)];                    // k==0 slot holds -1
            if (mg > bv[KTOP - 1]) {
                bv[KTOP - 1] = mg; bk[KTOP - 1] = k;
#pragma unroll
                for (int q = KTOP - 1; q > 0; q--) {
                    if (bv[q] > bv[q - 1]) {
                        float tv = bv[q]; bv[q] = bv[q - 1]; bv[q - 1] = tv;
                        int   tk = bk[q]; bk[q] = bk[q - 1]; bk[q - 1] = tk;
                    }
                }
            }
        }
        for (int r = 0; r < KTOP; r++) {
            float v = bv[0];
            int bestl = lane;
#pragma unroll
            for (int off = 16; off; off >>= 1) {
                float ov = __shfl_xor_sync(0xffffffffu, v, off);
                int   ol = __shfl_xor_sync(0xffffffffu, bestl, off);
                if (ov > v || (ov == v && ol < bestl)) { v = ov; bestl = ol; }
            }
            if (lane == bestl) {
                cand[(series << 4) + (half << 3) + r] =
                    make_float2(bv[0], __int_as_float(bk[0]));
#pragma unroll
                for (int q = 0; q < KTOP - 1; q++) { bv[q] = bv[q + 1]; bk[q] = bk[q + 1]; }
                bv[KTOP - 1] = -1.0f;
            }
        }
    }
    __syncthreads();

    // ---- Merge: warp = series, 16 candidates in lanes 0..15 ----
    if (tid < 128) {
        int series = wid;
        int odd    = series & 1;
        int hi     = series >> 1;
        float mv = -1.0f;
        int   mk = 1;
        if (lane < 16) {
            float2 cd = cand[(series << 4) + lane];
            mv = cd.x;
            mk = __float_as_int(cd.y);
        }
        int kout = 1;
        for (int r = 0; r < KTOP; r++) {
            float v = mv;
            int bestl = lane;
#pragma unroll
            for (int off = 16; off; off >>= 1) {
                float ov = __shfl_xor_sync(0xffffffffu, v, off);
                int   ol = __shfl_xor_sync(0xffffffffu, bestl, off);
                if (ov > v || (ov == v && ol < bestl)) { v = ov; bestl = ol; }
            }
            int wk = __shfl_sync(0xffffffffu, mk, bestl);
            if (lane == bestl) mv = -1.0f;
            if (lane == r) kout = wk;
        }
        if (lane < KTOP) {
            int k = kout;
            float4 t1 = X[XP(posk(k))];
            float4 t2 = X[XP(posk(2048 - k))];
            float2 z1 = hi ? make_float2(t1.z, t1.w) : make_float2(t1.x, t1.y);
            float2 z2 = hi ? make_float2(t2.z, t2.w) : make_float2(t2.x, t2.y);
            float Aa, Bb;
            const float inv = 1.0f / 2048.0f;
            if (odd == 0) { Aa = (z1.x + z2.x) * inv; Bb = (z1.y - z2.y) * inv; }
            else          { Aa = (z1.y + z2.y) * inv; Bb = (z2.x - z1.x) * inv; }
            float tc = 2.0f * cospif((float)k * (1.0f / 1024.0f));
            // component-major: [b][j=lane][d]
            g_comps[(b * KTOP + lane) * ND + 4 * dq + series] =
                make_float4((float)k, Aa, Bb, tc);
        }
    }
}

// ---------------------------------------------------------------------------
// Kernel C: Chebyshev-recurrence synthesis (step 1), 67-step chunks
// (2144 = 32 x 67). Coalesced [b][j][d] comps loads; 1 sincospif per
// harmonic (sin w recovered from shipped 2cos w).
// ---------------------------------------------------------------------------
__global__ void __launch_bounds__(128) k_synth(float* __restrict__ out) {
    int tid   = threadIdx.x;
    int b     = blockIdx.y;
    int d     = tid & 63;
    int chunk = blockIdx.x * 2 + (tid >> 6);   // 0..31
    int tt0   = chunk * 67;

    float c0[KTOP], c1[KTOP], tc[KTOP];
#pragma unroll
    for (int j = 0; j < KTOP; j++) {
        float4 cc = g_comps[(b * KTOP + j) * ND + d];   // warp: 512B contiguous
        int k = (int)cc.x;
        tc[j] = cc.w;                                   // 2 cos w
        float cw = 0.5f * cc.w;
        float sw = sqrtf(fmaxf(0.0f, 1.0f - cw * cw));  // sin w > 0 for k in 1..1023
        float s1, co1;
        sincospif((float)((k * tt0) & 2047) * (1.0f / 1024.0f), &s1, &co1);
        c1[j] = cc.y * co1 - cc.z * s1;                 // value at tt0
        float cm = co1 * cw + s1 * sw;                  // cos(th - w)
        float sm = s1 * cw - co1 * sw;                  // sin(th - w)
        c0[j] = cc.y * cm - cc.z * sm;                  // value at tt0 - 1
    }

    float* op = out + ((size_t)b * OUT_T + tt0) * ND + d;
#pragma unroll
    for (int c = 0; c < 66; c += 2) {
        float s1 = ((c1[0] + c1[1]) + (c1[2] + c1[3])) + ((c1[4] + c1[5]) + (c1[6] + c1[7]));
        op[(size_t)c * ND] = s1;
#pragma unroll
        for (int j = 0; j < KTOP; j++) c0[j] = fmaf(tc[j], c1[j], -c0[j]);
        float s2 = ((c0[0] + c0[1]) + (c0[2] + c0[3])) + ((c0[4] + c0[5]) + (c0[6] + c0[7]));
        op[(size_t)(c + 1) * ND] = s2;
#pragma unroll
        for (int j = 0; j < KTOP; j++) c1[j] = fmaf(tc[j], c0[j], -c1[j]);
    }
    // final step (c = 66): c1 holds value at tt0 + 66
    float sl = ((c1[0] + c1[1]) + (c1[2] + c1[3])) + ((c1[4] + c1[5]) + (c1[6] + c1[7]));
    op[(size_t)66 * ND] = sl;
}

// Nop kernel: 3 launches/replay puts the ncu capture window on k_fft_topk.
__global__ void k_nop() {}

// ---------------------------------------------------------------------------
extern "C" void kernel_launch(void* const* d_in, const int* in_sizes, int n_in,
                              void* d_out, int out_size) {
    const float* x = (const float*)d_in[0];
    float* out = (float*)d_out;

    const int FFT_SMEM = 36864 + 16896 + 512;   // 54272 B
    cudaFuncSetAttribute(k_fft_topk, cudaFuncAttributeMaxDynamicSharedMemorySize, FFT_SMEM);

    k_fft_topk<<<NB * 16, 256, FFT_SMEM>>>(x);
    k_synth<<<dim3(16, NB), 128>>>(out);
    k_nop<<<1, 32>>>();
}

// round 12
// speedup vs baseline: 1.0535x; 1.0535x over previous
#include <cuda_runtime.h>
#include <math.h>

#define NT     2048
#define NB     32
#define ND     64
#define OUT_T  2144
#define KTOP   8

// Padding: +1 per 8. <=2-way for all patterns; XP(8t+q) = 9t+q (contiguous).
#define XP(i) ((i) + ((i) >> 3))
// Mag-plane padding: +1 per 32
#define MP(i) ((i) + ((i) >> 5))

// Scratch (allocation-free): component-major layout [b][j][d] -> warp-coalesced
__device__ float4 g_comps[NB * KTOP * ND];     // {k, A, B, 2cos(w)}

__device__ __forceinline__ float2 cadd(float2 a, float2 b) { return make_float2(a.x + b.x, a.y + b.y); }
__device__ __forceinline__ float2 csub(float2 a, float2 b) { return make_float2(a.x - b.x, a.y - b.y); }
__device__ __forceinline__ float2 cmul(float2 a, float2 b) {
    return make_float2(a.x * b.x - a.y * b.y, a.x * b.y + a.y * b.x);
}
__device__ __forceinline__ float4 f4add(float4 a, float4 b) {
    return make_float4(a.x + b.x, a.y + b.y, a.z + b.z, a.w + b.w);
}
__device__ __forceinline__ float4 f4sub(float4 a, float4 b) {
    return make_float4(a.x - b.x, a.y - b.y, a.z - b.z, a.w - b.w);
}
__device__ __forceinline__ float4 cmul4(float4 a, float2 w) {
    return make_float4(a.x * w.x - a.y * w.y, a.x * w.y + a.y * w.x,
                       a.z * w.x - a.w * w.y, a.z * w.y + a.w * w.x);
}
__device__ __forceinline__ float4 pk(float2 lo, float2 hi, float2 w) {
    float2 a = cmul(lo, w), b = cmul(hi, w);
    return make_float4(a.x, a.y, b.x, b.y);
}

// scalar dft8
__device__ __forceinline__ void dft8(const float2* a, float2* y) {
    float2 z0 = cadd(a[0], a[4]), z1 = csub(a[0], a[4]);
    float2 z2 = cadd(a[2], a[6]), z3 = csub(a[2], a[6]);
    float2 E0 = cadd(z0, z2), E2 = csub(z0, z2);
    float2 E1 = make_float2(z1.x + z3.y, z1.y - z3.x);
    float2 E3 = make_float2(z1.x - z3.y, z1.y + z3.x);
    float2 u0 = cadd(a[1], a[5]), u1 = csub(a[1], a[5]);
    float2 u2 = cadd(a[3], a[7]), u3 = csub(a[3], a[7]);
    float2 O0 = cadd(u0, u2), O2 = csub(u0, u2);
    float2 O1 = make_float2(u1.x + u3.y, u1.y - u3.x);
    float2 O3 = make_float2(u1.x - u3.y, u1.y + u3.x);
    const float s = 0.70710678118654752f;
    float2 T1 = make_float2(s * (O1.x + O1.y), s * (O1.y - O1.x));
    float2 T2 = make_float2(O2.y, -O2.x);
    float2 T3 = make_float2(s * (O3.y - O3.x), -s * (O3.x + O3.y));
    y[0] = cadd(E0, O0); y[4] = csub(E0, O0);
    y[1] = cadd(E1, T1); y[5] = csub(E1, T1);
    y[2] = cadd(E2, T2); y[6] = csub(E2, T2);
    y[3] = cadd(E3, T3); y[7] = csub(E3, T3);
}

// dual (float4) dft8
__device__ __forceinline__ void dft8_4(const float4* a, float4* y) {
    float4 z0 = f4add(a[0], a[4]), z1 = f4sub(a[0], a[4]);
    float4 z2 = f4add(a[2], a[6]), z3 = f4sub(a[2], a[6]);
    float4 E0 = f4add(z0, z2), E2 = f4sub(z0, z2);
    float4 E1 = make_float4(z1.x + z3.y, z1.y - z3.x, z1.z + z3.w, z1.w - z3.z);
    float4 E3 = make_float4(z1.x - z3.y, z1.y + z3.x, z1.z - z3.w, z1.w + z3.z);
    float4 u0 = f4add(a[1], a[5]), u1 = f4sub(a[1], a[5]);
    float4 u2 = f4add(a[3], a[7]), u3 = f4sub(a[3], a[7]);
    float4 O0 = f4add(u0, u2), O2 = f4sub(u0, u2);
    float4 O1 = make_float4(u1.x + u3.y, u1.y - u3.x, u1.z + u3.w, u1.w - u3.z);
    float4 O3 = make_float4(u1.x - u3.y, u1.y + u3.x, u1.z - u3.w, u1.w + u3.z);
    const float s = 0.70710678118654752f;
    float4 T1 = make_float4(s * (O1.x + O1.y), s * (O1.y - O1.x),
                            s * (O1.z + O1.w), s * (O1.w - O1.z));
    float4 T2 = make_float4(O2.y, -O2.x, O2.w, -O2.z);
    float4 T3 = make_float4(s * (O3.y - O3.x), -s * (O3.x + O3.y),
                            s * (O3.w - O3.z), -s * (O3.z + O3.w));
    y[0] = f4add(E0, O0); y[4] = f4sub(E0, O0);
    y[1] = f4add(E1, T1); y[5] = f4sub(E1, T1);
    y[2] = f4add(E2, T2); y[6] = f4sub(E2, T2);
    y[3] = f4add(E3, T3); y[7] = f4sub(E3, T3);
}

// Output position of frequency k (mixed-radix 8,8,4,8 DIF digit reversal)
__device__ __forceinline__ int posk(int k) {
    return ((k >> 8) & 7) | (((k >> 6) & 3) << 3) | (((k >> 3) & 7) << 5) | ((k & 7) << 8);
}

// ---------------------------------------------------------------------------
// Kernel B: TWO packed-real-pair 2048-pt FFTs per block (4 series = one
// float4 column of (b,t,d)); single-pass magnitudes into 4 scalar planes.
// Dynamic smem: X(36864) + M(4x1056x4=16896) + cand(512) = 54272 B.
// ---------------------------------------------------------------------------
__global__ void __launch_bounds__(256) k_fft_topk(const float* __restrict__ x) {
    extern __shared__ char smem[];
    float4* X    = (float4*)smem;                       // XP-padded 2048
    float*  M    = (float*)(smem + 36864);              // 4 planes of MP-padded 1024
    float2* cand = (float2*)(smem + 36864 + 16896);     // 4 series x 16
    int tid  = threadIdx.x;
    int lane = tid & 31;
    int wid  = tid >> 5;
    int b    = blockIdx.x >> 4;
    int dq   = blockIdx.x & 15;         // float4 column: d = 4dq..4dq+3

    // ---- Stage 1: radix-8, stride 256, float4 from gmem; packed stores ----
    {
        float4 v[8];
        const float4* src4 = (const float4*)x + ((size_t)b * NT) * 16 + dq;
#pragma unroll
        for (int m = 0; m < 8; m++) v[m] = src4[(size_t)(tid + (m << 8)) * 16];
        float sw, cw;
        sincospif((float)tid * (1.0f / 1024.0f), &sw, &cw);
        float2 w1 = make_float2(cw, -sw);
        float2 w2 = cmul(w1, w1), w3 = cmul(w2, w1), w4 = cmul(w2, w2);
        float2 w5 = cmul(w3, w2), w6 = cmul(w3, w3), w7 = cmul(w4, w3);
        float2 a[8], lo[8], hi[8];
#pragma unroll
        for (int m = 0; m < 8; m++) a[m] = make_float2(v[m].x, v[m].y);
        dft8(a, lo);
#pragma unroll
        for (int m = 0; m < 8; m++) a[m] = make_float2(v[m].z, v[m].w);
        dft8(a, hi);
        X[XP(tid)]        = make_float4(lo[0].x, lo[0].y, hi[0].x, hi[0].y);
        X[XP(tid + 256)]  = pk(lo[1], hi[1], w1);
        X[XP(tid + 512)]  = pk(lo[2], hi[2], w2);
        X[XP(tid + 768)]  = pk(lo[3], hi[3], w3);
        X[XP(tid + 1024)] = pk(lo[4], hi[4], w4);
        X[XP(tid + 1280)] = pk(lo[5], hi[5], w5);
        X[XP(tid + 1536)] = pk(lo[6], hi[6], w6);
        X[XP(tid + 1792)] = pk(lo[7], hi[7], w7);
    }
    __syncthreads();

    // ---- Stage 2: radix-8, stride 32, within 256-blocks (float4) ----
    {
        int base = (wid << 8) + lane;
        float sw, cw;
        sincospif((float)lane * (1.0f / 128.0f), &sw, &cw);
        float2 w1 = make_float2(cw, -sw);
        float2 w2 = cmul(w1, w1), w3 = cmul(w2, w1), w4 = cmul(w2, w2);
        float2 w5 = cmul(w3, w2), w6 = cmul(w3, w3), w7 = cmul(w4, w3);
        float4 v[8], y[8];
#pragma unroll
        for (int m = 0; m < 8; m++) v[m] = X[XP(base + (m << 5))];
        dft8_4(v, y);
        X[XP(base)]       = y[0];
        X[XP(base + 32)]  = cmul4(y[1], w1);
        X[XP(base + 64)]  = cmul4(y[2], w2);
        X[XP(base + 96)]  = cmul4(y[3], w3);
        X[XP(base + 128)] = cmul4(y[4], w4);
        X[XP(base + 160)] = cmul4(y[5], w5);
        X[XP(base + 192)] = cmul4(y[6], w6);
        X[XP(base + 224)] = cmul4(y[7], w7);
    }
    __syncthreads();

    // ---- Stage 3: radix-4, stride 8 (twiddle depends on tid&7 only) ----
    {
        float sw, cw;
        sincospif((float)(tid & 7) * (1.0f / 16.0f), &sw, &cw);
        float2 w1 = make_float2(cw, -sw);
        float2 w2 = cmul(w1, w1), w3 = cmul(w2, w1);
#pragma unroll
        for (int n = 0; n < 2; n++) {
            int e = tid + (n << 8);
            int base = ((e >> 3) << 5) + (e & 7);
            float4 a = X[XP(base)],      bb = X[XP(base + 8)];
            float4 c = X[XP(base + 16)], d  = X[XP(base + 24)];
            float4 z0 = f4add(a, c), z1 = f4sub(a, c);
            float4 z2 = f4add(bb, d), z3 = f4sub(bb, d);
            float4 y0 = f4add(z0, z2), y2 = f4sub(z0, z2);
            float4 y1 = make_float4(z1.x + z3.y, z1.y - z3.x, z1.z + z3.w, z1.w - z3.z);
            float4 y3 = make_float4(z1.x - z3.y, z1.y + z3.x, z1.z - z3.w, z1.w + z3.z);
            X[XP(base)]      = y0;
            X[XP(base + 8)]  = cmul4(y1, w1);
            X[XP(base + 16)] = cmul4(y2, w2);
            X[XP(base + 24)] = cmul4(y3, w3);
        }
    }
    __syncthreads();

    // ---- Stage 4: radix-8 on 8 consecutive (XP(8t+q) = 9t+q) ----
    {
        int ph = 9 * tid;
        float4 v[8], y[8];
#pragma unroll
        for (int q = 0; q < 8; q++) v[q] = X[ph + q];
        dft8_4(v, y);
#pragma unroll
        for (int q = 0; q < 8; q++) X[ph + q] = y[q];
    }
    __syncthreads();

    // ---- Magnitudes, single pass: all 4 series from one X-pair load ----
    {
        int basek = (lane << 5) | (wid << 2);
        int pb = XP(posk(basek));                    // k-side: +288 per q (exact)
        int mb = MP(basek);                          // +1 per q (k>>5 fixed)
#pragma unroll
        for (int q = 0; q < 4; q++) {
            int k = basek + q;
            float m0, m1, m2, m3;
            if (k == 0) {
                m0 = m1 = m2 = m3 = -1.0f;
            } else {
                float4 t1 = X[pb + 288 * q];
                float4 t2 = X[XP(posk(2048 - k))];
                float e0r = t1.x + t2.x, e0i = t1.y - t2.y;
                float o0r = t1.y + t2.y, o0i = t2.x - t1.x;
                float e1r = t1.z + t2.z, e1i = t1.w - t2.w;
                float o1r = t1.w + t2.w, o1i = t2.z - t1.z;
                m0 = fmaf(e0r, e0r, e0i * e0i);
                m1 = fmaf(o0r, o0r, o0i * o0i);
                m2 = fmaf(e1r, e1r, e1i * e1i);
                m3 = fmaf(o1r, o1r, o1i * o1i);
            }
            int mi = mb + q;
            M[mi]        = m0;
            M[1056 + mi] = m1;
            M[2112 + mi] = m2;
            M[3168 + mi] = m3;
        }
    }
    __syncthreads();

    // ---- Scan: warp w -> series w>>1, half w&1; consecutive k, scalar LDS ----
    {
        int series = wid >> 1;
        int half   = wid & 1;
        const float* Mp = M + series * 1056;
        float bv[KTOP];
        int   bk[KTOP];
#pragma unroll
        for (int q = 0; q < KTOP; q++) { bv[q] = -1.0f; bk[q] = 1; }
#pragma unroll
        for (int it = 0; it < 16; it++) {
            int k = (half << 9) | (it << 5) | lane;
            float mg = Mp[MP(k)];                    // k==0 slot holds -1
            if (mg > bv[KTOP - 1]) {
                bv[KTOP - 1] = mg; bk[KTOP - 1] = k;
#pragma unroll
                for (int q = KTOP - 1; q > 0; q--) {
                    if (bv[q] > bv[q - 1]) {
                        float tv = bv[q]; bv[q] = bv[q - 1]; bv[q - 1] = tv;
                        int   tk = bk[q]; bk[q] = bk[q - 1]; bk[q - 1] = tk;
                    }
                }
            }
        }
        for (int r = 0; r < KTOP; r++) {
            float v = bv[0];
            int bestl = lane;
#pragma unroll
            for (int off = 16; off; off >>= 1) {
                float ov = __shfl_xor_sync(0xffffffffu, v, off);
                int   ol = __shfl_xor_sync(0xffffffffu, bestl, off);
                if (ov > v || (ov == v && ol < bestl)) { v = ov; bestl = ol; }
            }
            if (lane == bestl) {
                cand[(series << 4) + (half << 3) + r] =
                    make_float2(bv[0], __int_as_float(bk[0]));
#pragma unroll
                for (int q = 0; q < KTOP - 1; q++) { bv[q] = bv[q + 1]; bk[q] = bk[q + 1]; }
                bv[KTOP - 1] = -1.0f;
            }
        }
    }
    __syncthreads();

    // ---- Merge: warp = series, 16 candidates in lanes 0..15 ----
    if (tid < 128) {
        int series = wid;
        int odd    = series & 1;
        int hi     = series >> 1;
        float mv = -1.0f;
        int   mk = 1;
        if (lane < 16) {
            float2 cd = cand[(series << 4) + lane];
            mv = cd.x;
            mk = __float_as_int(cd.y);
        }
        int kout = 1;
        for (int r = 0; r < KTOP; r++) {
            float v = mv;
            int bestl = lane;
#pragma unroll
            for (int off = 16; off; off >>= 1) {
                float ov = __shfl_xor_sync(0xffffffffu, v, off);
                int   ol = __shfl_xor_sync(0xffffffffu, bestl, off);
                if (ov > v || (ov == v && ol < bestl)) { v = ov; bestl = ol; }
            }
            int wk = __shfl_sync(0xffffffffu, mk, bestl);
            if (lane == bestl) mv = -1.0f;
            if (lane == r) kout = wk;
        }
        if (lane < KTOP) {
            int k = kout;
            float4 t1 = X[XP(posk(k))];
            float4 t2 = X[XP(posk(2048 - k))];
            float2 z1 = hi ? make_float2(t1.z, t1.w) : make_float2(t1.x, t1.y);
            float2 z2 = hi ? make_float2(t2.z, t2.w) : make_float2(t2.x, t2.y);
            float Aa, Bb;
            const float inv = 1.0f / 2048.0f;
            if (odd == 0) { Aa = (z1.x + z2.x) * inv; Bb = (z1.y - z2.y) * inv; }
            else          { Aa = (z1.y + z2.y) * inv; Bb = (z2.x - z1.x) * inv; }
            float tc = 2.0f * cospif((float)k * (1.0f / 1024.0f));
            // component-major: [b][j=lane][d]
            g_comps[(b * KTOP + lane) * ND + 4 * dq + series] =
                make_float4((float)k, Aa, Bb, tc);
        }
    }
}

// ---------------------------------------------------------------------------
// Kernel C: Chebyshev-recurrence synthesis (step 1), 67-step chunks
// (2144 = 32 x 67). Coalesced [b][j][d] comps loads; 1 sincospif per
// harmonic (sin w recovered from shipped 2cos w).
// ---------------------------------------------------------------------------
__global__ void __launch_bounds__(128) k_synth(float* __restrict__ out) {
    int tid   = threadIdx.x;
    int b     = blockIdx.y;
    int d     = tid & 63;
    int chunk = blockIdx.x * 2 + (tid >> 6);   // 0..31
    int tt0   = chunk * 67;

    float c0[KTOP], c1[KTOP], tc[KTOP];
#pragma unroll
    for (int j = 0; j < KTOP; j++) {
        float4 cc = g_comps[(b * KTOP + j) * ND + d];   // warp: 512B contiguous
        int k = (int)cc.x;
        tc[j] = cc.w;                                   // 2 cos w
        float cw = 0.5f * cc.w;
        float sw = sqrtf(fmaxf(0.0f, 1.0f - cw * cw));  // sin w > 0 for k in 1..1023
        float s1, co1;
        sincospif((float)((k * tt0) & 2047) * (1.0f / 1024.0f), &s1, &co1);
        c1[j] = cc.y * co1 - cc.z * s1;                 // value at tt0
        float cm = co1 * cw + s1 * sw;                  // cos(th - w)
        float sm = s1 * cw - co1 * sw;                  // sin(th - w)
        c0[j] = cc.y * cm - cc.z * sm;                  // value at tt0 - 1
    }

    float* op = out + ((size_t)b * OUT_T + tt0) * ND + d;
#pragma unroll
    for (int c = 0; c < 66; c += 2) {
        float s1 = ((c1[0] + c1[1]) + (c1[2] + c1[3])) + ((c1[4] + c1[5]) + (c1[6] + c1[7]));
        op[(size_t)c * ND] = s1;
#pragma unroll
        for (int j = 0; j < KTOP; j++) c0[j] = fmaf(tc[j], c1[j], -c0[j]);
        float s2 = ((c0[0] + c0[1]) + (c0[2] + c0[3])) + ((c0[4] + c0[5]) + (c0[6] + c0[7]));
        op[(size_t)(c + 1) * ND] = s2;
#pragma unroll
        for (int j = 0; j < KTOP; j++) c1[j] = fmaf(tc[j], c0[j], -c1[j]);
    }
    // final step (c = 66): c1 holds value at tt0 + 66
    float sl = ((c1[0] + c1[1]) + (c1[2] + c1[3])) + ((c1[4] + c1[5]) + (c1[6] + c1[7]));
    op[(size_t)66 * ND] = sl;
}

// ---------------------------------------------------------------------------
extern "C" void kernel_launch(void* const* d_in, const int* in_sizes, int n_in,
                              void* d_out, int out_size) {
    const float* x = (const float*)d_in[0];
    float* out = (float*)d_out;

    const int FFT_SMEM = 36864 + 16896 + 512;   // 54272 B
    cudaFuncSetAttribute(k_fft_topk, cudaFuncAttributeMaxDynamicSharedMemorySize, FFT_SMEM);

    k_fft_topk<<<NB * 16, 256, FFT_SMEM>>>(x);
    k_synth<<<dim3(16, NB), 128>>>(out);
}

// round 13
// speedup vs baseline: 1.0616x; 1.0077x over previous
#include <cuda_runtime.h>
#include <math.h>

#define NT     2048
#define NB     32
#define ND     64
#define OUT_T  2144
#define KTOP   8

// Padding: +1 per 8. <=2-way for all patterns; XP(8t+q) = 9t+q (contiguous).
#define XP(i) ((i) + ((i) >> 3))
// Mag-plane padding: +1 per 32
#define MP(i) ((i) + ((i) >> 5))

// Scratch (allocation-free): component-major layout [b][j][d] -> warp-coalesced
__device__ float4 g_comps[NB * KTOP * ND];     // {k, A, B, 2cos(w)}

__device__ __forceinline__ float2 cadd(float2 a, float2 b) { return make_float2(a.x + b.x, a.y + b.y); }
__device__ __forceinline__ float2 csub(float2 a, float2 b) { return make_float2(a.x - b.x, a.y - b.y); }
__device__ __forceinline__ float2 cmul(float2 a, float2 b) {
    return make_float2(a.x * b.x - a.y * b.y, a.x * b.y + a.y * b.x);
}
__device__ __forceinline__ float4 f4add(float4 a, float4 b) {
    return make_float4(a.x + b.x, a.y + b.y, a.z + b.z, a.w + b.w);
}
__device__ __forceinline__ float4 f4sub(float4 a, float4 b) {
    return make_float4(a.x - b.x, a.y - b.y, a.z - b.z, a.w - b.w);
}
__device__ __forceinline__ float4 cmul4(float4 a, float2 w) {
    return make_float4(a.x * w.x - a.y * w.y, a.x * w.y + a.y * w.x,
                       a.z * w.x - a.w * w.y, a.z * w.y + a.w * w.x);
}
__device__ __forceinline__ float4 pk(float2 lo, float2 hi, float2 w) {
    float2 a = cmul(lo, w), b = cmul(hi, w);
    return make_float4(a.x, a.y, b.x, b.y);
}

// scalar dft8
__device__ __forceinline__ void dft8(const float2* a, float2* y) {
    float2 z0 = cadd(a[0], a[4]), z1 = csub(a[0], a[4]);
    float2 z2 = cadd(a[2], a[6]), z3 = csub(a[2], a[6]);
    float2 E0 = cadd(z0, z2), E2 = csub(z0, z2);
    float2 E1 = make_float2(z1.x + z3.y, z1.y - z3.x);
    float2 E3 = make_float2(z1.x - z3.y, z1.y + z3.x);
    float2 u0 = cadd(a[1], a[5]), u1 = csub(a[1], a[5]);
    float2 u2 = cadd(a[3], a[7]), u3 = csub(a[3], a[7]);
    float2 O0 = cadd(u0, u2), O2 = csub(u0, u2);
    float2 O1 = make_float2(u1.x + u3.y, u1.y - u3.x);
    float2 O3 = make_float2(u1.x - u3.y, u1.y + u3.x);
    const float s = 0.70710678118654752f;
    float2 T1 = make_float2(s * (O1.x + O1.y), s * (O1.y - O1.x));
    float2 T2 = make_float2(O2.y, -O2.x);
    float2 T3 = make_float2(s * (O3.y - O3.x), -s * (O3.x + O3.y));
    y[0] = cadd(E0, O0); y[4] = csub(E0, O0);
    y[1] = cadd(E1, T1); y[5] = csub(E1, T1);
    y[2] = cadd(E2, T2); y[6] = csub(E2, T2);
    y[3] = cadd(E3, T3); y[7] = csub(E3, T3);
}

// dual (float4) dft8
__device__ __forceinline__ void dft8_4(const float4* a, float4* y) {
    float4 z0 = f4add(a[0], a[4]), z1 = f4sub(a[0], a[4]);
    float4 z2 = f4add(a[2], a[6]), z3 = f4sub(a[2], a[6]);
    float4 E0 = f4add(z0, z2), E2 = f4sub(z0, z2);
    float4 E1 = make_float4(z1.x + z3.y, z1.y - z3.x, z1.z + z3.w, z1.w - z3.z);
    float4 E3 = make_float4(z1.x - z3.y, z1.y + z3.x, z1.z - z3.w, z1.w + z3.z);
    float4 u0 = f4add(a[1], a[5]), u1 = f4sub(a[1], a[5]);
    float4 u2 = f4add(a[3], a[7]), u3 = f4sub(a[3], a[7]);
    float4 O0 = f4add(u0, u2), O2 = f4sub(u0, u2);
    float4 O1 = make_float4(u1.x + u3.y, u1.y - u3.x, u1.z + u3.w, u1.w - u3.z);
    float4 O3 = make_float4(u1.x - u3.y, u1.y + u3.x, u1.z - u3.w, u1.w + u3.z);
    const float s = 0.70710678118654752f;
    float4 T1 = make_float4(s * (O1.x + O1.y), s * (O1.y - O1.x),
                            s * (O1.z + O1.w), s * (O1.w - O1.z));
    float4 T2 = make_float4(O2.y, -O2.x, O2.w, -O2.z);
    float4 T3 = make_float4(s * (O3.y - O3.x), -s * (O3.x + O3.y),
                            s * (O3.w - O3.z), -s * (O3.z + O3.w));
    y[0] = f4add(E0, O0); y[4] = f4sub(E0, O0);
    y[1] = f4add(E1, T1); y[5] = f4sub(E1, T1);
    y[2] = f4add(E2, T2); y[6] = f4sub(E2, T2);
    y[3] = f4add(E3, T3); y[7] = f4sub(E3, T3);
}

// Output position of frequency k (mixed-radix 8,8,4,8 DIF digit reversal)
__device__ __forceinline__ int posk(int k) {
    return ((k >> 8) & 7) | (((k >> 6) & 3) << 3) | (((k >> 3) & 7) << 5) | ((k & 7) << 8);
}

// ---------------------------------------------------------------------------
// Kernel B: TWO packed-real-pair 2048-pt FFTs per block (4 series = one
// float4 column of (b,t,d)); single-pass magnitudes into 4 scalar planes.
// Dynamic smem: X(36864) + M(4x1056x4=16896) + cand(512) = 54272 B.
// ---------------------------------------------------------------------------
__global__ void __launch_bounds__(256) k_fft_topk(const float* __restrict__ x) {
    extern __shared__ char smem[];
    float4* X    = (float4*)smem;                       // XP-padded 2048
    float*  M    = (float*)(smem + 36864);              // 4 planes of MP-padded 1024
    float2* cand = (float2*)(smem + 36864 + 16896);     // 4 series x 16
    int tid  = threadIdx.x;
    int lane = tid & 31;
    int wid  = tid >> 5;
    int b    = blockIdx.x >> 4;
    int dq   = blockIdx.x & 15;         // float4 column: d = 4dq..4dq+3

    // ---- Stage 1: radix-8, stride 256, float4 from gmem; packed stores ----
    {
        float4 v[8];
        const float4* src4 = (const float4*)x + ((size_t)b * NT) * 16 + dq;
#pragma unroll
        for (int m = 0; m < 8; m++) v[m] = src4[(size_t)(tid + (m << 8)) * 16];
        float sw, cw;
        sincospif((float)tid * (1.0f / 1024.0f), &sw, &cw);
        float2 w1 = make_float2(cw, -sw);
        float2 w2 = cmul(w1, w1), w3 = cmul(w2, w1), w4 = cmul(w2, w2);
        float2 w5 = cmul(w3, w2), w6 = cmul(w3, w3), w7 = cmul(w4, w3);
        float2 a[8], lo[8], hi[8];
#pragma unroll
        for (int m = 0; m < 8; m++) a[m] = make_float2(v[m].x, v[m].y);
        dft8(a, lo);
#pragma unroll
        for (int m = 0; m < 8; m++) a[m] = make_float2(v[m].z, v[m].w);
        dft8(a, hi);
        X[XP(tid)]        = make_float4(lo[0].x, lo[0].y, hi[0].x, hi[0].y);
        X[XP(tid + 256)]  = pk(lo[1], hi[1], w1);
        X[XP(tid + 512)]  = pk(lo[2], hi[2], w2);
        X[XP(tid + 768)]  = pk(lo[3], hi[3], w3);
        X[XP(tid + 1024)] = pk(lo[4], hi[4], w4);
        X[XP(tid + 1280)] = pk(lo[5], hi[5], w5);
        X[XP(tid + 1536)] = pk(lo[6], hi[6], w6);
        X[XP(tid + 1792)] = pk(lo[7], hi[7], w7);
    }
    __syncthreads();

    // ---- Stage 2: radix-8, stride 32, within 256-blocks (float4) ----
    {
        int base = (wid << 8) + lane;
        float sw, cw;
        sincospif((float)lane * (1.0f / 128.0f), &sw, &cw);
        float2 w1 = make_float2(cw, -sw);
        float2 w2 = cmul(w1, w1), w3 = cmul(w2, w1), w4 = cmul(w2, w2);
        float2 w5 = cmul(w3, w2), w6 = cmul(w3, w3), w7 = cmul(w4, w3);
        float4 v[8], y[8];
#pragma unroll
        for (int m = 0; m < 8; m++) v[m] = X[XP(base + (m << 5))];
        dft8_4(v, y);
        X[XP(base)]       = y[0];
        X[XP(base + 32)]  = cmul4(y[1], w1);
        X[XP(base + 64)]  = cmul4(y[2], w2);
        X[XP(base + 96)]  = cmul4(y[3], w3);
        X[XP(base + 128)] = cmul4(y[4], w4);
        X[XP(base + 160)] = cmul4(y[5], w5);
        X[XP(base + 192)] = cmul4(y[6], w6);
        X[XP(base + 224)] = cmul4(y[7], w7);
    }
    __syncthreads();

    // ---- Stage 3: radix-4, stride 8 (twiddle depends on tid&7 only) ----
    {
        float sw, cw;
        sincospif((float)(tid & 7) * (1.0f / 16.0f), &sw, &cw);
        float2 w1 = make_float2(cw, -sw);
        float2 w2 = cmul(w1, w1), w3 = cmul(w2, w1);
#pragma unroll
        for (int n = 0; n < 2; n++) {
            int e = tid + (n << 8);
            int base = ((e >> 3) << 5) + (e & 7);
            float4 a = X[XP(base)],      bb = X[XP(base + 8)];
            float4 c = X[XP(base + 16)], d  = X[XP(base + 24)];
            float4 z0 = f4add(a, c), z1 = f4sub(a, c);
            float4 z2 = f4add(bb, d), z3 = f4sub(bb, d);
            float4 y0 = f4add(z0, z2), y2 = f4sub(z0, z2);
            float4 y1 = make_float4(z1.x + z3.y, z1.y - z3.x, z1.z + z3.w, z1.w - z3.z);
            float4 y3 = make_float4(z1.x - z3.y, z1.y + z3.x, z1.z - z3.w, z1.w + z3.z);
            X[XP(base)]      = y0;
            X[XP(base + 8)]  = cmul4(y1, w1);
            X[XP(base + 16)] = cmul4(y2, w2);
            X[XP(base + 24)] = cmul4(y3, w3);
        }
    }
    __syncthreads();

    // ---- Stage 4: radix-8 on 8 consecutive (XP(8t+q) = 9t+q) ----
    {
        int ph = 9 * tid;
        float4 v[8], y[8];
#pragma unroll
        for (int q = 0; q < 8; q++) v[q] = X[ph + q];
        dft8_4(v, y);
#pragma unroll
        for (int q = 0; q < 8; q++) X[ph + q] = y[q];
    }
    __syncthreads();

    // ---- Magnitudes, single pass: all 4 series from one X-pair load ----
    {
        int basek = (lane << 5) | (wid << 2);
        int pb = XP(posk(basek));                    // k-side: +288 per q (exact)
        int mb = MP(basek);                          // +1 per q (k>>5 fixed)
#pragma unroll
        for (int q = 0; q < 4; q++) {
            int k = basek + q;
            float m0, m1, m2, m3;
            if (k == 0) {
                m0 = m1 = m2 = m3 = -1.0f;
            } else {
                float4 t1 = X[pb + 288 * q];
                float4 t2 = X[XP(posk(2048 - k))];
                float e0r = t1.x + t2.x, e0i = t1.y - t2.y;
                float o0r = t1.y + t2.y, o0i = t2.x - t1.x;
                float e1r = t1.z + t2.z, e1i = t1.w - t2.w;
                float o1r = t1.w + t2.w, o1i = t2.z - t1.z;
                m0 = fmaf(e0r, e0r, e0i * e0i);
                m1 = fmaf(o0r, o0r, o0i * o0i);
                m2 = fmaf(e1r, e1r, e1i * e1i);
                m3 = fmaf(o1r, o1r, o1i * o1i);
            }
            int mi = mb + q;
            M[mi]        = m0;
            M[1056 + mi] = m1;
            M[2112 + mi] = m2;
            M[3168 + mi] = m3;
        }
    }
    __syncthreads();

    // ---- Scan: warp w -> series w>>1, half w&1; consecutive k, scalar LDS ----
    {
        int series = wid >> 1;
        int half   = wid & 1;
        const float* Mp = M + series * 1056;
        float bv[KTOP];
        int   bk[KTOP];
#pragma unroll
        for (int q = 0; q < KTOP; q++) { bv[q] = -1.0f; bk[q] = 1; }
#pragma unroll
        for (int it = 0; it < 16; it++) {
            int k = (half << 9) | (it << 5) | lane;
            float mg = Mp[MP(k)];                    // k==0 slot holds -1
            if (mg > bv[KTOP - 1]) {
                bv[KTOP - 1] = mg; bk[KTOP - 1] = k;
#pragma unroll
                for (int q = KTOP - 1; q > 0; q--) {
                    if (bv[q] > bv[q - 1]) {
                        float tv = bv[q]; bv[q] = bv[q - 1]; bv[q - 1] = tv;
                        int   tk = bk[q]; bk[q] = bk[q - 1]; bk[q - 1] = tk;
                    }
                }
            }
        }
        for (int r = 0; r < KTOP; r++) {
            float v = bv[0];
            int bestl = lane;
#pragma unroll
            for (int off = 16; off; off >>= 1) {
                float ov = __shfl_xor_sync(0xffffffffu, v, off);
                int   ol = __shfl_xor_sync(0xffffffffu, bestl, off);
                if (ov > v || (ov == v && ol < bestl)) { v = ov; bestl = ol; }
            }
            if (lane == bestl) {
                cand[(series << 4) + (half << 3) + r] =
                    make_float2(bv[0], __int_as_float(bk[0]));
#pragma unroll
                for (int q = 0; q < KTOP - 1; q++) { bv[q] = bv[q + 1]; bk[q] = bk[q + 1]; }
                bv[KTOP - 1] = -1.0f;
            }
        }
    }
    __syncthreads();

    // ---- Merge: warp = series, 16 candidates in lanes 0..15 ----
    if (tid < 128) {
        int series = wid;
        int odd    = series & 1;
        int hi     = series >> 1;
        float mv = -1.0f;
        int   mk = 1;
        if (lane < 16) {
            float2 cd = cand[(series << 4) + lane];
            mv = cd.x;
            mk = __float_as_int(cd.y);
        }
        int kout = 1;
        for (int r = 0; r < KTOP; r++) {
            float v = mv;
            int bestl = lane;
#pragma unroll
            for (int off = 16; off; off >>= 1) {
                float ov = __shfl_xor_sync(0xffffffffu, v, off);
                int   ol = __shfl_xor_sync(0xffffffffu, bestl, off);
                if (ov > v || (ov == v && ol < bestl)) { v = ov; bestl = ol; }
            }
            int wk = __shfl_sync(0xffffffffu, mk, bestl);
            if (lane == bestl) mv = -1.0f;
            if (lane == r) kout = wk;
        }
        if (lane < KTOP) {
            int k = kout;
            float4 t1 = X[XP(posk(k))];
            float4 t2 = X[XP(posk(2048 - k))];
            float2 z1 = hi ? make_float2(t1.z, t1.w) : make_float2(t1.x, t1.y);
            float2 z2 = hi ? make_float2(t2.z, t2.w) : make_float2(t2.x, t2.y);
            float Aa, Bb;
            const float inv = 1.0f / 2048.0f;
            if (odd == 0) { Aa = (z1.x + z2.x) * inv; Bb = (z1.y - z2.y) * inv; }
            else          { Aa = (z1.y + z2.y) * inv; Bb = (z2.x - z1.x) * inv; }
            float tc = 2.0f * cospif((float)k * (1.0f / 1024.0f));
            // component-major: [b][j=lane][d]
            g_comps[(b * KTOP + lane) * ND + 4 * dq + series] =
                make_float4((float)k, Aa, Bb, tc);
        }
    }
}

// ---------------------------------------------------------------------------
// Kernel C: Chebyshev-recurrence synthesis (step 1), 67-step chunks
// (2144 = 32 x 67). Coalesced [b][j][d] comps loads. Seeds via __sincosf
// (MUFU, constant-offset error only); recurrence coefficient tc stays the
// FFT-shipped 1-ulp 2cos(w) (coefficient error is what compounds).
// ---------------------------------------------------------------------------
__global__ void __launch_bounds__(128) k_synth(float* __restrict__ out) {
    int tid   = threadIdx.x;
    int b     = blockIdx.y;
    int d     = tid & 63;
    int chunk = blockIdx.x * 2 + (tid >> 6);   // 0..31
    int tt0   = chunk * 67;

    const float PI_1024 = 3.14159265358979323846f / 1024.0f;
    float c0[KTOP], c1[KTOP], tc[KTOP];
#pragma unroll
    for (int j = 0; j < KTOP; j++) {
        float4 cc = g_comps[(b * KTOP + j) * ND + d];   // warp: 512B contiguous
        int k = (int)cc.x;
        tc[j] = cc.w;                                   // accurate 2 cos w
        // theta = pi*k*tt0/1024 reduced to (-pi, pi]
        int m = ((k * tt0 + 1024) & 2047) - 1024;
        float s1, co1;
        __sincosf((float)m * PI_1024, &s1, &co1);
        float sw, cw;
        __sincosf((float)k * PI_1024, &sw, &cw);        // w in (0, pi)
        c1[j] = cc.y * co1 - cc.z * s1;                 // value at tt0
        float cm = co1 * cw + s1 * sw;                  // cos(th - w)
        float sm = s1 * cw - co1 * sw;                  // sin(th - w)
        c0[j] = cc.y * cm - cc.z * sm;                  // value at tt0 - 1
    }

    float* op = out + ((size_t)b * OUT_T + tt0) * ND + d;
#pragma unroll
    for (int c = 0; c < 66; c += 2) {
        float s1 = ((c1[0] + c1[1]) + (c1[2] + c1[3])) + ((c1[4] + c1[5]) + (c1[6] + c1[7]));
        op[(size_t)c * ND] = s1;
#pragma unroll
        for (int j = 0; j < KTOP; j++) c0[j] = fmaf(tc[j], c1[j], -c0[j]);
        float s2 = ((c0[0] + c0[1]) + (c0[2] + c0[3])) + ((c0[4] + c0[5]) + (c0[6] + c0[7]));
        op[(size_t)(c + 1) * ND] = s2;
#pragma unroll
        for (int j = 0; j < KTOP; j++) c1[j] = fmaf(tc[j], c0[j], -c1[j]);
    }
    // final step (c = 66): c1 holds value at tt0 + 66
    float sl = ((c1[0] + c1[1]) + (c1[2] + c1[3])) + ((c1[4] + c1[5]) + (c1[6] + c1[7]));
    op[(size_t)66 * ND] = sl;
}

// ---------------------------------------------------------------------------
extern "C" void kernel_launch(void* const* d_in, const int* in_sizes, int n_in,
                              void* d_out, int out_size) {
    const float* x = (const float*)d_in[0];
    float* out = (float*)d_out;

    const int FFT_SMEM = 36864 + 16896 + 512;   // 54272 B
    cudaFuncSetAttribute(k_fft_topk, cudaFuncAttributeMaxDynamicSharedMemorySize, FFT_SMEM);

    k_fft_topk<<<NB * 16, 256, FFT_SMEM>>>(x);
    k_synth<<<dim3(16, NB), 128>>>(out);
}

// round 14
// speedup vs baseline: 1.1209x; 1.0559x over previous
#include <cuda_runtime.h>
#include <math.h>

#define NT     2048
#define NB     32
#define ND     64
#define OUT_T  2144
#define KTOP   8

// Padding: +1 per 8. <=2-way for all patterns; XP(8t+q) = 9t+q (contiguous).
#define XP(i) ((i) + ((i) >> 3))
// Mag-plane padding: +1 per 32
#define MP(i) ((i) + ((i) >> 5))

// Scratch (allocation-free): component-major layout [b][j][d] -> warp-coalesced
__device__ float4 g_comps[NB * KTOP * ND];     // {k, A, B, 2cos(w)}

__device__ __forceinline__ float2 cadd(float2 a, float2 b) { return make_float2(a.x + b.x, a.y + b.y); }
__device__ __forceinline__ float2 csub(float2 a, float2 b) { return make_float2(a.x - b.x, a.y - b.y); }
__device__ __forceinline__ float2 cmul(float2 a, float2 b) {
    return make_float2(a.x * b.x - a.y * b.y, a.x * b.y + a.y * b.x);
}
__device__ __forceinline__ float4 f4add(float4 a, float4 b) {
    return make_float4(a.x + b.x, a.y + b.y, a.z + b.z, a.w + b.w);
}
__device__ __forceinline__ float4 f4sub(float4 a, float4 b) {
    return make_float4(a.x - b.x, a.y - b.y, a.z - b.z, a.w - b.w);
}
__device__ __forceinline__ float4 cmul4(float4 a, float2 w) {
    return make_float4(a.x * w.x - a.y * w.y, a.x * w.y + a.y * w.x,
                       a.z * w.x - a.w * w.y, a.z * w.y + a.w * w.x);
}
__device__ __forceinline__ float4 pk(float2 lo, float2 hi, float2 w) {
    float2 a = cmul(lo, w), b = cmul(hi, w);
    return make_float4(a.x, a.y, b.x, b.y);
}

// scalar dft8
__device__ __forceinline__ void dft8(const float2* a, float2* y) {
    float2 z0 = cadd(a[0], a[4]), z1 = csub(a[0], a[4]);
    float2 z2 = cadd(a[2], a[6]), z3 = csub(a[2], a[6]);
    float2 E0 = cadd(z0, z2), E2 = csub(z0, z2);
    float2 E1 = make_float2(z1.x + z3.y, z1.y - z3.x);
    float2 E3 = make_float2(z1.x - z3.y, z1.y + z3.x);
    float2 u0 = cadd(a[1], a[5]), u1 = csub(a[1], a[5]);
    float2 u2 = cadd(a[3], a[7]), u3 = csub(a[3], a[7]);
    float2 O0 = cadd(u0, u2), O2 = csub(u0, u2);
    float2 O1 = make_float2(u1.x + u3.y, u1.y - u3.x);
    float2 O3 = make_float2(u1.x - u3.y, u1.y + u3.x);
    const float s = 0.70710678118654752f;
    float2 T1 = make_float2(s * (O1.x + O1.y), s * (O1.y - O1.x));
    float2 T2 = make_float2(O2.y, -O2.x);
    float2 T3 = make_float2(s * (O3.y - O3.x), -s * (O3.x + O3.y));
    y[0] = cadd(E0, O0); y[4] = csub(E0, O0);
    y[1] = cadd(E1, T1); y[5] = csub(E1, T1);
    y[2] = cadd(E2, T2); y[6] = csub(E2, T2);
    y[3] = cadd(E3, T3); y[7] = csub(E3, T3);
}

// dual (float4) dft8
__device__ __forceinline__ void dft8_4(const float4* a, float4* y) {
    float4 z0 = f4add(a[0], a[4]), z1 = f4sub(a[0], a[4]);
    float4 z2 = f4add(a[2], a[6]), z3 = f4sub(a[2], a[6]);
    float4 E0 = f4add(z0, z2), E2 = f4sub(z0, z2);
    float4 E1 = make_float4(z1.x + z3.y, z1.y - z3.x, z1.z + z3.w, z1.w - z3.z);
    float4 E3 = make_float4(z1.x - z3.y, z1.y + z3.x, z1.z - z3.w, z1.w + z3.z);
    float4 u0 = f4add(a[1], a[5]), u1 = f4sub(a[1], a[5]);
    float4 u2 = f4add(a[3], a[7]), u3 = f4sub(a[3], a[7]);
    float4 O0 = f4add(u0, u2), O2 = f4sub(u0, u2);
    float4 O1 = make_float4(u1.x + u3.y, u1.y - u3.x, u1.z + u3.w, u1.w - u3.z);
    float4 O3 = make_float4(u1.x - u3.y, u1.y + u3.x, u1.z - u3.w, u1.w + u3.z);
    const float s = 0.70710678118654752f;
    float4 T1 = make_float4(s * (O1.x + O1.y), s * (O1.y - O1.x),
                            s * (O1.z + O1.w), s * (O1.w - O1.z));
    float4 T2 = make_float4(O2.y, -O2.x, O2.w, -O2.z);
    float4 T3 = make_float4(s * (O3.y - O3.x), -s * (O3.x + O3.y),
                            s * (O3.w - O3.z), -s * (O3.z + O3.w));
    y[0] = f4add(E0, O0); y[4] = f4sub(E0, O0);
    y[1] = f4add(E1, T1); y[5] = f4sub(E1, T1);
    y[2] = f4add(E2, T2); y[6] = f4sub(E2, T2);
    y[3] = f4add(E3, T3); y[7] = f4sub(E3, T3);
}

// Output position of frequency k (mixed-radix 8,8,4,8 DIF digit reversal)
__device__ __forceinline__ int posk(int k) {
    return ((k >> 8) & 7) | (((k >> 6) & 3) << 3) | (((k >> 3) & 7) << 5) | ((k & 7) << 8);
}

// ---------------------------------------------------------------------------
// Kernel B: TWO packed-real-pair 2048-pt FFTs per block (4 series = one
// float4 column of (b,t,d)); single-pass magnitudes into 4 scalar planes.
// Dynamic smem: X(36864) + M(4x1056x4=16896) + cand(512) = 54272 B.
// ---------------------------------------------------------------------------
__global__ void __launch_bounds__(256) k_fft_topk(const float* __restrict__ x) {
    extern __shared__ char smem[];
    float4* X    = (float4*)smem;                       // XP-padded 2048
    float*  M    = (float*)(smem + 36864);              // 4 planes of MP-padded 1024
    float2* cand = (float2*)(smem + 36864 + 16896);     // 4 series x 16
    int tid  = threadIdx.x;
    int lane = tid & 31;
    int wid  = tid >> 5;
    int b    = blockIdx.x >> 4;
    int dq   = blockIdx.x & 15;         // float4 column: d = 4dq..4dq+3

    // ---- Stage 1: radix-8, stride 256, float4 from gmem; packed stores ----
    {
        float4 v[8];
        const float4* src4 = (const float4*)x + ((size_t)b * NT) * 16 + dq;
#pragma unroll
        for (int m = 0; m < 8; m++) v[m] = src4[(size_t)(tid + (m << 8)) * 16];
        float sw, cw;
        sincospif((float)tid * (1.0f / 1024.0f), &sw, &cw);
        float2 w1 = make_float2(cw, -sw);
        float2 w2 = cmul(w1, w1), w3 = cmul(w2, w1), w4 = cmul(w2, w2);
        float2 w5 = cmul(w3, w2), w6 = cmul(w3, w3), w7 = cmul(w4, w3);
        float2 a[8], lo[8], hi[8];
#pragma unroll
        for (int m = 0; m < 8; m++) a[m] = make_float2(v[m].x, v[m].y);
        dft8(a, lo);
#pragma unroll
        for (int m = 0; m < 8; m++) a[m] = make_float2(v[m].z, v[m].w);
        dft8(a, hi);
        X[XP(tid)]        = make_float4(lo[0].x, lo[0].y, hi[0].x, hi[0].y);
        X[XP(tid + 256)]  = pk(lo[1], hi[1], w1);
        X[XP(tid + 512)]  = pk(lo[2], hi[2], w2);
        X[XP(tid + 768)]  = pk(lo[3], hi[3], w3);
        X[XP(tid + 1024)] = pk(lo[4], hi[4], w4);
        X[XP(tid + 1280)] = pk(lo[5], hi[5], w5);
        X[XP(tid + 1536)] = pk(lo[6], hi[6], w6);
        X[XP(tid + 1792)] = pk(lo[7], hi[7], w7);
    }
    __syncthreads();

    // ---- Stage 2: radix-8, stride 32, within 256-blocks (float4) ----
    {
        int base = (wid << 8) + lane;
        float sw, cw;
        sincospif((float)lane * (1.0f / 128.0f), &sw, &cw);
        float2 w1 = make_float2(cw, -sw);
        float2 w2 = cmul(w1, w1), w3 = cmul(w2, w1), w4 = cmul(w2, w2);
        float2 w5 = cmul(w3, w2), w6 = cmul(w3, w3), w7 = cmul(w4, w3);
        float4 v[8], y[8];
#pragma unroll
        for (int m = 0; m < 8; m++) v[m] = X[XP(base + (m << 5))];
        dft8_4(v, y);
        X[XP(base)]       = y[0];
        X[XP(base + 32)]  = cmul4(y[1], w1);
        X[XP(base + 64)]  = cmul4(y[2], w2);
        X[XP(base + 96)]  = cmul4(y[3], w3);
        X[XP(base + 128)] = cmul4(y[4], w4);
        X[XP(base + 160)] = cmul4(y[5], w5);
        X[XP(base + 192)] = cmul4(y[6], w6);
        X[XP(base + 224)] = cmul4(y[7], w7);
    }
    __syncthreads();

    // ---- Stage 3: radix-4, stride 8 (twiddle depends on tid&7 only) ----
    {
        float sw, cw;
        sincospif((float)(tid & 7) * (1.0f / 16.0f), &sw, &cw);
        float2 w1 = make_float2(cw, -sw);
        float2 w2 = cmul(w1, w1), w3 = cmul(w2, w1);
#pragma unroll
        for (int n = 0; n < 2; n++) {
            int e = tid + (n << 8);
            int base = ((e >> 3) << 5) + (e & 7);
            float4 a = X[XP(base)],      bb = X[XP(base + 8)];
            float4 c = X[XP(base + 16)], d  = X[XP(base + 24)];
            float4 z0 = f4add(a, c), z1 = f4sub(a, c);
            float4 z2 = f4add(bb, d), z3 = f4sub(bb, d);
            float4 y0 = f4add(z0, z2), y2 = f4sub(z0, z2);
            float4 y1 = make_float4(z1.x + z3.y, z1.y - z3.x, z1.z + z3.w, z1.w - z3.z);
            float4 y3 = make_float4(z1.x - z3.y, z1.y + z3.x, z1.z - z3.w, z1.w + z3.z);
            X[XP(base)]      = y0;
            X[XP(base + 8)]  = cmul4(y1, w1);
            X[XP(base + 16)] = cmul4(y2, w2);
            X[XP(base + 24)] = cmul4(y3, w3);
        }
    }
    __syncthreads();

    // ---- Stage 4: radix-8 on 8 consecutive (XP(8t+q) = 9t+q) ----
    {
        int ph = 9 * tid;
        float4 v[8], y[8];
#pragma unroll
        for (int q = 0; q < 8; q++) v[q] = X[ph + q];
        dft8_4(v, y);
#pragma unroll
        for (int q = 0; q < 8; q++) X[ph + q] = y[q];
    }
    __syncthreads();

    // ---- Magnitudes, single pass: all 4 series from one X-pair load ----
    {
        int basek = (lane << 5) | (wid << 2);
        int pb = XP(posk(basek));                    // k-side: +288 per q (exact)
        int mb = MP(basek);                          // +1 per q (k>>5 fixed)
#pragma unroll
        for (int q = 0; q < 4; q++) {
            int k = basek + q;
            float m0, m1, m2, m3;
            if (k == 0) {
                m0 = m1 = m2 = m3 = -1.0f;
            } else {
                float4 t1 = X[pb + 288 * q];
                float4 t2 = X[XP(posk(2048 - k))];
                float e0r = t1.x + t2.x, e0i = t1.y - t2.y;
                float o0r = t1.y + t2.y, o0i = t2.x - t1.x;
                float e1r = t1.z + t2.z, e1i = t1.w - t2.w;
                float o1r = t1.w + t2.w, o1i = t2.z - t1.z;
                m0 = fmaf(e0r, e0r, e0i * e0i);
                m1 = fmaf(o0r, o0r, o0i * o0i);
                m2 = fmaf(e1r, e1r, e1i * e1i);
                m3 = fmaf(o1r, o1r, o1i * o1i);
            }
            int mi = mb + q;
            M[mi]        = m0;
            M[1056 + mi] = m1;
            M[2112 + mi] = m2;
            M[3168 + mi] = m3;
        }
    }
    __syncthreads();

    // ---- Scan: warp w -> series w>>1, half w&1; consecutive k, scalar LDS ----
    {
        int series = wid >> 1;
        int half   = wid & 1;
        const float* Mp = M + series * 1056;
        float bv[KTOP];
        int   bk[KTOP];
#pragma unroll
        for (int q = 0; q < KTOP; q++) { bv[q] = -1.0f; bk[q] = 1; }
#pragma unroll
        for (int it = 0; it < 16; it++) {
            int k = (half << 9) | (it << 5) | lane;
            float mg = Mp[MP(k)];                    // k==0 slot holds -1
            if (mg > bv[KTOP - 1]) {
                bv[KTOP - 1] = mg; bk[KTOP - 1] = k;
#pragma unroll
                for (int q = KTOP - 1; q > 0; q--) {
                    if (bv[q] > bv[q - 1]) {
                        float tv = bv[q]; bv[q] = bv[q - 1]; bv[q - 1] = tv;
                        int   tk = bk[q]; bk[q] = bk[q - 1]; bk[q - 1] = tk;
                    }
                }
            }
        }
        for (int r = 0; r < KTOP; r++) {
            float v = bv[0];
            int bestl = lane;
#pragma unroll
            for (int off = 16; off; off >>= 1) {
                float ov = __shfl_xor_sync(0xffffffffu, v, off);
                int   ol = __shfl_xor_sync(0xffffffffu, bestl, off);
                if (ov > v || (ov == v && ol < bestl)) { v = ov; bestl = ol; }
            }
            if (lane == bestl) {
                cand[(series << 4) + (half << 3) + r] =
                    make_float2(bv[0], __int_as_float(bk[0]));
#pragma unroll
                for (int q = 0; q < KTOP - 1; q++) { bv[q] = bv[q + 1]; bk[q] = bk[q + 1]; }
                bv[KTOP - 1] = -1.0f;
            }
        }
    }
    __syncthreads();

    // ---- Merge: warp = series, 16 candidates in lanes 0..15 ----
    if (tid < 128) {
        int series = wid;
        int odd    = series & 1;
        int hi     = series >> 1;
        float mv = -1.0f;
        int   mk = 1;
        if (lane < 16) {
            float2 cd = cand[(series << 4) + lane];
            mv = cd.x;
            mk = __float_as_int(cd.y);
        }
        int kout = 1;
        for (int r = 0; r < KTOP; r++) {
            float v = mv;
            int bestl = lane;
#pragma unroll
            for (int off = 16; off; off >>= 1) {
                float ov = __shfl_xor_sync(0xffffffffu, v, off);
                int   ol = __shfl_xor_sync(0xffffffffu, bestl, off);
                if (ov > v || (ov == v && ol < bestl)) { v = ov; bestl = ol; }
            }
            int wk = __shfl_sync(0xffffffffu, mk, bestl);
            if (lane == bestl) mv = -1.0f;
            if (lane == r) kout = wk;
        }
        if (lane < KTOP) {
            int k = kout;
            float4 t1 = X[XP(posk(k))];
            float4 t2 = X[XP(posk(2048 - k))];
            float2 z1 = hi ? make_float2(t1.z, t1.w) : make_float2(t1.x, t1.y);
            float2 z2 = hi ? make_float2(t2.z, t2.w) : make_float2(t2.x, t2.y);
            float Aa, Bb;
            const float inv = 1.0f / 2048.0f;
            if (odd == 0) { Aa = (z1.x + z2.x) * inv; Bb = (z1.y - z2.y) * inv; }
            else          { Aa = (z1.y + z2.y) * inv; Bb = (z2.x - z1.x) * inv; }
            float tc = 2.0f * cospif((float)k * (1.0f / 1024.0f));
            // component-major: [b][j=lane][d]
            g_comps[(b * KTOP + lane) * ND + 4 * dq + series] =
                make_float4((float)k, Aa, Bb, tc);
        }
    }
}

// ---------------------------------------------------------------------------
// Kernel C: Chebyshev-recurrence synthesis (step 1), 34-step chunks
// (64 chunks cover 2144; last chunk is short -> predicated stores).
// 2x the warps of the 67-chunk version; seeds via __sincosf (MUFU).
// Recurrence coefficient tc stays the FFT-shipped 1-ulp 2cos(w).
// ---------------------------------------------------------------------------
__global__ void __launch_bounds__(128) k_synth(float* __restrict__ out) {
    int tid   = threadIdx.x;
    int b     = blockIdx.y;
    int d     = tid & 63;
    int chunk = blockIdx.x * 2 + (tid >> 6);   // 0..63
    int tt0   = chunk * 34;                    // last chunk: tt0 = 2142, 2 valid
    int nt    = OUT_T - tt0;                   // >= 2; uniform per warp

    const float PI_1024 = 3.14159265358979323846f / 1024.0f;
    float c0[KTOP], c1[KTOP], tc[KTOP];
#pragma unroll
    for (int j = 0; j < KTOP; j++) {
        float4 cc = g_comps[(b * KTOP + j) * ND + d];   // warp: 512B contiguous
        int k = (int)cc.x;
        tc[j] = cc.w;                                   // accurate 2 cos w
        // theta = pi*k*tt0/1024 reduced to (-pi, pi]
        int m = ((k * tt0 + 1024) & 2047) - 1024;
        float s1, co1;
        __sincosf((float)m * PI_1024, &s1, &co1);
        float sw, cw;
        __sincosf((float)k * PI_1024, &sw, &cw);        // w in (0, pi)
        c1[j] = cc.y * co1 - cc.z * s1;                 // value at tt0
        float cm = co1 * cw + s1 * sw;                  // cos(th - w)
        float sm = s1 * cw - co1 * sw;                  // sin(th - w)
        c0[j] = cc.y * cm - cc.z * sm;                  // value at tt0 - 1
    }

    float* op = out + ((size_t)b * OUT_T + tt0) * ND + d;
#pragma unroll
    for (int c = 0; c < 34; c += 2) {
        float s1 = ((c1[0] + c1[1]) + (c1[2] + c1[3])) + ((c1[4] + c1[5]) + (c1[6] + c1[7]));
        if (c < nt) op[(size_t)c * ND] = s1;
#pragma unroll
        for (int j = 0; j < KTOP; j++) c0[j] = fmaf(tc[j], c1[j], -c0[j]);
        float s2 = ((c0[0] + c0[1]) + (c0[2] + c0[3])) + ((c0[4] + c0[5]) + (c0[6] + c0[7]));
        if (c + 1 < nt) op[(size_t)(c + 1) * ND] = s2;
#pragma unroll
        for (int j = 0; j < KTOP; j++) c1[j] = fmaf(tc[j], c0[j], -c1[j]);
    }
}

// ---------------------------------------------------------------------------
extern "C" void kernel_launch(void* const* d_in, const int* in_sizes, int n_in,
                              void* d_out, int out_size) {
    const float* x = (const float*)d_in[0];
    float* out = (float*)d_out;

    const int FFT_SMEM = 36864 + 16896 + 512;   // 54272 B
    cudaFuncSetAttribute(k_fft_topk, cudaFuncAttributeMaxDynamicSharedMemorySize, FFT_SMEM);

    k_fft_topk<<<NB * 16, 256, FFT_SMEM>>>(x);
    k_synth<<<dim3(32, NB), 128>>>(out);
}